// round 13
// baseline (speedup 1.0000x reference)
#include <cuda_runtime.h>
#include <cuda_bf16.h>
#include <cstdint>

// ---------------------------------------------------------------------------
// BottleneckModel decomposed implementation (fp32 + packed f32x2 FFMA)
// Shapes: B=16, L=64, P=512, H=16, DH=32, DIM=128, CDIM=256, inner=512, PEH=64
//
// Pipeline:
//   prep_w1t: transpose w_mlp1 once into scratch (coalesced reload per block)
//   sgemm64: qk  = h_ligand @ w_qk          [1024,512]
//   sgemm64: cqk = context  @ w_cqk         [8192,512]
//   sgemm64: cv  = context  @ w_cv          [8192,512]
//   sim_kernel: sim[b,h,l,p] = (qk . cqk)*scale   (batched GEMM, cqk reused over l)
//   fused_attn: PE-MLP + attn-MLP + softmax + dis path; writes attn[0:16]
//   av_kernel: outpre[b,l,h,d] = attn @ cv        (batched GEMM, cv reused over l)
//   sgemm64: out = outpre @ w_out + b_out
//
// Canonical score layout: g_sim/g_attn element (b,h,l,p) at
//   ((b*16 + h)*64 + l)*512 + p
// ---------------------------------------------------------------------------

#define BB   16
#define LL   64
#define PP   512
#define HH   16
#define DHH  32
#define DIMM 128
#define CDIMM 256
#define INNER 512
#define PEH  64

typedef unsigned long long ull;

// Scratch (device globals; no allocation allowed)
__device__ float g_qk[BB * LL * INNER];          // [1024, 512]
__device__ float g_cqk[BB * PP * INNER];         // [8192, 512]
__device__ float g_cv[BB * PP * INNER];          // [8192, 512]
__device__ float g_sim[BB * HH * LL * PP];       // [b][h][l][p]
__device__ float g_attn[BB * HH * LL * PP];      // [b][h][l][p] (heads 0..15)
__device__ float g_outpre[BB * LL * INNER];      // [b*64+l][h*32+d]
__device__ float g_w1t[32 * 64];                 // transposed w_mlp1: [j][i]

// ---- packed fp32x2 helpers (Blackwell packed FFMA pipe) ----
__device__ __forceinline__ ull pack2(float lo, float hi) {
    ull r; asm("mov.b64 %0, {%1, %2};" : "=l"(r) : "f"(lo), "f"(hi)); return r;
}
__device__ __forceinline__ void unpack2(ull v, float& lo, float& hi) {
    asm("mov.b64 {%0, %1}, %2;" : "=f"(lo), "=f"(hi) : "l"(v));
}
__device__ __forceinline__ ull fma2(ull a, ull b, ull c) {
    ull d; asm("fma.rn.f32x2 %0, %1, %2, %3;" : "=l"(d) : "l"(a), "l"(b), "l"(c)); return d;
}

__device__ __forceinline__ float mishf(float x) {
    // mish(x) = x * tanh(softplus(x)) = x * (e^2 + 2e) / (e^2 + 2e + 2), e = exp(x)
    float e = __expf(fminf(x, 15.0f));
    float n = e * e + 2.0f * e;
    return x * __fdividef(n, n + 2.0f);
}

// ---------------------------------------------------------------------------
// prep kernel: w1t[j*32+i] = w_mlp1[i*64+j] (done once; blocks reload coalesced)
// ---------------------------------------------------------------------------
__global__ __launch_bounds__(256) void prep_w1t(const float* __restrict__ w_mlp1)
{
    int i = blockIdx.x * 256 + threadIdx.x;   // 2048 total
    if (i < 2048)
        g_w1t[i] = w_mlp1[((i & 31) << 6) + (i >> 5)];
}

// ---------------------------------------------------------------------------
// Tiled SGEMM: C[M,N] = A[M,K] @ B[K,N] (+bias)
// BM=BN=64, BK=16, 256 threads, 4x4 micro-tile, packed FFMA2 inner product.
// Register-prefetched global loads (next k-tile LDG overlaps current compute).
// All smem operand reads are 16B LDS.128 (3 per kk-step vs 8 fma2).
// ---------------------------------------------------------------------------
__global__ __launch_bounds__(256) void sgemm64(
    const float* __restrict__ A, const float* __restrict__ Bm,
    float* __restrict__ C, int M, int N, int K, const float* __restrict__ bias)
{
    __shared__ ull  As2[16][64];   // A value duplicated into both halves
    __shared__ float Bs[16][64];

    const int tid = threadIdx.x;
    const int row0 = blockIdx.y * 64, col0 = blockIdx.x * 64;
    const int ty = tid / 16, tx = tid % 16;
    const int aRow = tid / 4, aCol = (tid % 4) * 4;
    const int bRow = tid / 16, bCol = (tid % 16) * 4;

    ull acc2[4][2] = {};

    // prefetch tile 0
    float4 av = *(const float4*)(A + (size_t)(row0 + aRow) * K + aCol);
    float4 bvv = *(const float4*)(Bm + (size_t)bRow * N + col0 + bCol);

    for (int k0 = 0; k0 < K; k0 += 16) {
        As2[aCol + 0][aRow] = pack2(av.x, av.x);
        As2[aCol + 1][aRow] = pack2(av.y, av.y);
        As2[aCol + 2][aRow] = pack2(av.z, av.z);
        As2[aCol + 3][aRow] = pack2(av.w, av.w);
        *(float4*)(&Bs[bRow][bCol]) = bvv;
        __syncthreads();
        // prefetch next tile while computing this one
        if (k0 + 16 < K) {
            av  = *(const float4*)(A + (size_t)(row0 + aRow) * K + k0 + 16 + aCol);
            bvv = *(const float4*)(Bm + (size_t)(k0 + 16 + bRow) * N + col0 + bCol);
        }
        #pragma unroll
        for (int kk = 0; kk < 16; kk++) {
            // one LDS.128 for the B pair, two LDS.128 for the four A ulls
            ulonglong2 bb = *(const ulonglong2*)(&Bs[kk][tx * 4]);
            const ulonglong2* arow = (const ulonglong2*)(&As2[kk][ty * 4]);
            ulonglong2 a01 = arow[0], a23 = arow[1];
            acc2[0][0] = fma2(a01.x, bb.x, acc2[0][0]);
            acc2[0][1] = fma2(a01.x, bb.y, acc2[0][1]);
            acc2[1][0] = fma2(a01.y, bb.x, acc2[1][0]);
            acc2[1][1] = fma2(a01.y, bb.y, acc2[1][1]);
            acc2[2][0] = fma2(a23.x, bb.x, acc2[2][0]);
            acc2[2][1] = fma2(a23.x, bb.y, acc2[2][1]);
            acc2[3][0] = fma2(a23.y, bb.x, acc2[3][0]);
            acc2[3][1] = fma2(a23.y, bb.y, acc2[3][1]);
        }
        __syncthreads();
    }

    float4 bv = make_float4(0.f, 0.f, 0.f, 0.f);
    if (bias) bv = *(const float4*)(bias + col0 + tx * 4);
    #pragma unroll
    for (int i = 0; i < 4; i++) {
        float4 v;
        unpack2(acc2[i][0], v.x, v.y);
        unpack2(acc2[i][1], v.z, v.w);
        v.x += bv.x; v.y += bv.y; v.z += bv.z; v.w += bv.w;
        *(float4*)(C + (size_t)(row0 + ty * 4 + i) * N + col0 + tx * 4) = v;
    }
}

// ---------------------------------------------------------------------------
// sim_kernel: per (b,h) block computes sim[b][h][l][p] = scale * qk . cqk
// [64,32] @ [32,512]^T, tiled over p in chunks of 128.
// ---------------------------------------------------------------------------
__global__ __launch_bounds__(256) void sim_kernel(
    const float* __restrict__ qk, const float* __restrict__ cqk,
    float* __restrict__ sim)
{
    const int blk = blockIdx.x, b = blk >> 4, h = blk & 15;
    __shared__ float aq[64][33];     // prescaled qk tile
    __shared__ float cq[128][33];
    const int t = threadIdx.x, ty = t >> 5, tx = t & 31;
    const float scale = 0.17677669529663687f;  // 32^-0.5

    for (int i = t; i < 2048; i += 256) {
        int l = i >> 5, d = i & 31;
        aq[l][d] = qk[((size_t)(b * 64 + l)) * INNER + h * 32 + d] * scale;
    }

    for (int p0 = 0; p0 < PP; p0 += 128) {
        __syncthreads();
        for (int i = t; i < 4096; i += 256) {
            int pp = i >> 5, d = i & 31;
            cq[pp][d] = cqk[((size_t)(b * PP + p0 + pp)) * INNER + h * 32 + d];
        }
        __syncthreads();
        ull acc2[8][2] = {};
        #pragma unroll 4
        for (int k = 0; k < 32; k++) {
            float c0 = cq[tx][k], c1 = cq[tx + 32][k];
            float c2 = cq[tx + 64][k], c3 = cq[tx + 96][k];
            ull cc0 = pack2(c0, c1), cc1 = pack2(c2, c3);
            #pragma unroll
            for (int i = 0; i < 8; i++) {
                float a = aq[ty * 8 + i][k];
                ull aa = pack2(a, a);
                acc2[i][0] = fma2(aa, cc0, acc2[i][0]);
                acc2[i][1] = fma2(aa, cc1, acc2[i][1]);
            }
        }
        #pragma unroll
        for (int i = 0; i < 8; i++) {
            float v0, v1, v2, v3;
            unpack2(acc2[i][0], v0, v1);
            unpack2(acc2[i][1], v2, v3);
            size_t base = ((size_t)(b * 16 + h) * 64 + ty * 8 + i) * PP + p0;
            sim[base + tx]      = v0;
            sim[base + tx + 32] = v1;
            sim[base + tx + 64] = v2;
            sim[base + tx + 96] = v3;
        }
    }
}

// ---------------------------------------------------------------------------
// av_kernel: per (b,h): outpre[l][d] = sum_p attn[b][h][l][p] * cv[b][p][h*32+d]
// [64,512] @ [512,32], 128 threads, 4x4 micro-tile, packed f32x2.
// ---------------------------------------------------------------------------
__global__ __launch_bounds__(128) void av_kernel(
    const float* __restrict__ attn, const float* __restrict__ cv,
    float* __restrict__ outpre)
{
    const int blk = blockIdx.x, b = blk >> 4, h = blk & 15;
    __shared__ float at[64][65];     // [l][k]
    __shared__ float cvs[64][36];    // [k][d]; stride 36 keeps dg*4 16B-aligned
    const int t = threadIdx.x;
    const int lg = t >> 3, dg = t & 7;   // l = lg*4+i, d = dg*4+j

    ull acc2[4][2] = {};

    for (int k0 = 0; k0 < PP; k0 += 64) {
        __syncthreads();
        for (int i4 = t; i4 < 1024; i4 += 128) {
            int l = i4 >> 4, kk4 = (i4 & 15) * 4;
            float4 v = *(const float4*)(
                attn + ((size_t)(b * 16 + h) * 64 + l) * PP + k0 + kk4);
            at[l][kk4]     = v.x;
            at[l][kk4 + 1] = v.y;
            at[l][kk4 + 2] = v.z;
            at[l][kk4 + 3] = v.w;
        }
        for (int i = t; i < 2048; i += 128) {
            int kk = i >> 5, d = i & 31;
            cvs[kk][d] = cv[((size_t)(b * PP + k0 + kk)) * INNER + h * 32 + d];
        }
        __syncthreads();
        #pragma unroll 4
        for (int kk = 0; kk < 64; kk++) {
            // one LDS.128 gets both cv ull pairs
            ulonglong2 cc = *(const ulonglong2*)(&cvs[kk][dg * 4]);
            #pragma unroll
            for (int i = 0; i < 4; i++) {
                float a = at[lg * 4 + i][kk];
                ull aa = pack2(a, a);
                acc2[i][0] = fma2(aa, cc.x, acc2[i][0]);
                acc2[i][1] = fma2(aa, cc.y, acc2[i][1]);
            }
        }
    }

    #pragma unroll
    for (int i = 0; i < 4; i++) {
        float4 v;
        unpack2(acc2[i][0], v.x, v.y);
        unpack2(acc2[i][1], v.z, v.w);
        *(float4*)(outpre + ((size_t)(b * 64 + lg * 4 + i)) * INNER
                   + h * 32 + dg * 4) = v;
    }
}

// ---------------------------------------------------------------------------
// Fused core: one block per (b,l). 256 threads.
// Each thread jointly processes p and p+256 so every broadcast weight LDS is
// amortized over two score columns (halves LSU issue in the MLP loops).
// ---------------------------------------------------------------------------
struct SmemLayout {
    float s2[32 * 513];      // padded stride; offset 0 (16B aligned)
    float w1[32 * 64];       // TRANSPOSED: w1[j*32 + i] = w_mlp1[i*64 + j]
    float w2[64 * 32];       // [j][c]
    float b2[32];
    float wp1[3 * 64];
    float bp1[64];
    float wp2[64 * 16];      // [j][h]
    float bp2[16];
    float wd1[16 * 32];
    float bd1[32];
    float wd2[32 * 16];
    float bd2[16];
    float xp[PP * 3];
    float odis[48];
};

__global__ __launch_bounds__(256) void fused_attn_kernel(
    const float* __restrict__ x_protein,
    const float* __restrict__ x_ligand,
    const float* __restrict__ w_mlp2,
    const float* __restrict__ b_mlp2,
    const float* __restrict__ w_dis1, const float* __restrict__ b_dis1,
    const float* __restrict__ w_dis2, const float* __restrict__ b_dis2,
    const float* __restrict__ sigma,
    const float* __restrict__ w_pe1, const float* __restrict__ b_pe1,
    const float* __restrict__ w_pe2, const float* __restrict__ b_pe2,
    float* __restrict__ out_dis)
{
    extern __shared__ float smem_raw[];
    SmemLayout& s = *reinterpret_cast<SmemLayout*>(smem_raw);

    const int t = threadIdx.x;
    const int blk = blockIdx.x;          // b*L + l
    const int bb = blk / LL;
    const int ll = blk % LL;

    // ---- cooperative loads (all coalesced) ----
    for (int i = t; i < 2048; i += 256) {
        s.w1[i] = g_w1t[i];          // pre-transposed
        s.w2[i] = w_mlp2[i];
    }
    for (int i = t; i < 1024; i += 256) s.wp2[i] = w_pe2[i];
    for (int i = t; i < 512; i += 256) { s.wd1[i] = w_dis1[i]; s.wd2[i] = w_dis2[i]; }
    if (t < 192) s.wp1[t] = w_pe1[t];
    if (t < 64)  s.bp1[t] = b_pe1[t];
    if (t < 32)  { s.b2[t] = b_mlp2[t]; s.bd1[t] = b_dis1[t]; }
    if (t < 16)  { s.bp2[t] = b_pe2[t]; s.bd2[t] = b_dis2[t]; }
    for (int i = t; i < PP * 3; i += 256)
        s.xp[i] = x_protein[(size_t)bb * PP * 3 + i];

    const float xl0 = x_ligand[blk * 3 + 0];
    const float xl1 = x_ligand[blk * 3 + 1];
    const float xl2 = x_ligand[blk * 3 + 2];
    const float sg = sigma[0];
    const float sfac = -0.5f / (sg * sg);
    __syncthreads();

    // Canonical score base for (b, h=0, l): ((bb*16+0)*64 + ll) * PP
    const size_t scoreBase = ((size_t)bb * (HH * LL) + ll) * PP;

    // ---- Phase 1: sim load + PE MLP + attn MLP for p0=t and p1=t+256 ----
    {
        const int p0 = t, p1 = t + 256;
        const float* simbase = g_sim + scoreBase;

        ull sc2a[16], sc2b[16];
        {
            float sha[16], shb[16];
            #pragma unroll
            for (int h = 0; h < HH; h++) {
                const float* r = simbase + (size_t)h * (LL * PP);
                sha[h] = r[p0];
                shb[h] = r[p1];
            }
            #pragma unroll
            for (int h2 = 0; h2 < 8; h2++) {
                sc2a[h2] = pack2(sha[2 * h2], sha[2 * h2 + 1]);
                sc2b[h2] = pack2(shb[2 * h2], shb[2 * h2 + 1]);
            }
        }

        // positional-encoding inputs for both columns
        float ea0 = __expf(sfac * (s.xp[p0 * 3 + 0] - xl0));
        float ea1 = __expf(sfac * (s.xp[p0 * 3 + 1] - xl1));
        float ea2 = __expf(sfac * (s.xp[p0 * 3 + 2] - xl2));
        float eb0 = __expf(sfac * (s.xp[p1 * 3 + 0] - xl0));
        float eb1 = __expf(sfac * (s.xp[p1 * 3 + 1] - xl1));
        float eb2 = __expf(sfac * (s.xp[p1 * 3 + 2] - xl2));

        #pragma unroll
        for (int h2 = 0; h2 < 8; h2++) {
            ull bv = pack2(s.bp2[2 * h2], s.bp2[2 * h2 + 1]);
            sc2a[8 + h2] = bv;
            sc2b[8 + h2] = bv;
        }

        // PE MLP: 3 -> 64 (mish) -> 16, weights loaded once per j for both p
        #pragma unroll 1
        for (int j = 0; j < PEH; j++) {
            float w0 = s.wp1[j], w1v = s.wp1[64 + j], w2v = s.wp1[128 + j];
            float bj = s.bp1[j];
            float hma = mishf(bj + ea0 * w0 + ea1 * w1v + ea2 * w2v);
            float hmb = mishf(bj + eb0 * w0 + eb1 * w1v + eb2 * w2v);
            ull hm2a = pack2(hma, hma), hm2b = pack2(hmb, hmb);
            const ulonglong2* wp = (const ulonglong2*)(s.wp2 + j * 16);
            #pragma unroll
            for (int h4 = 0; h4 < 4; h4++) {
                ulonglong2 w = wp[h4];
                sc2a[8 + 2 * h4]     = fma2(hm2a, w.x, sc2a[8 + 2 * h4]);
                sc2a[8 + 2 * h4 + 1] = fma2(hm2a, w.y, sc2a[8 + 2 * h4 + 1]);
                sc2b[8 + 2 * h4]     = fma2(hm2b, w.x, sc2b[8 + 2 * h4]);
                sc2b[8 + 2 * h4 + 1] = fma2(hm2b, w.y, sc2b[8 + 2 * h4 + 1]);
            }
        }

        // attn MLP: 32 -> 64 (mish) -> 32, weights loaded once per j for both p
        ull o2a[16], o2b[16];
        #pragma unroll
        for (int c2 = 0; c2 < 16; c2++) {
            ull bv = pack2(s.b2[2 * c2], s.b2[2 * c2 + 1]);
            o2a[c2] = bv;
            o2b[c2] = bv;
        }
        #pragma unroll 1
        for (int j = 0; j < 64; j++) {
            const ulonglong2* w1p = (const ulonglong2*)(s.w1 + j * 32);
            ull taa = 0ull, tab = 0ull, tba = 0ull, tbb = 0ull;
            #pragma unroll
            for (int i4 = 0; i4 < 8; i4++) {
                ulonglong2 w = w1p[i4];
                taa = fma2(sc2a[2 * i4],     w.x, taa);
                tab = fma2(sc2a[2 * i4 + 1], w.y, tab);
                tba = fma2(sc2b[2 * i4],     w.x, tba);
                tbb = fma2(sc2b[2 * i4 + 1], w.y, tbb);
            }
            float x0, x1, y0, y1;
            unpack2(taa, x0, x1); unpack2(tab, y0, y1);
            float hma = mishf((x0 + x1) + (y0 + y1));
            unpack2(tba, x0, x1); unpack2(tbb, y0, y1);
            float hmb = mishf((x0 + x1) + (y0 + y1));
            ull hm2a = pack2(hma, hma), hm2b = pack2(hmb, hmb);
            const ulonglong2* w2p = (const ulonglong2*)(s.w2 + j * 32);
            #pragma unroll
            for (int c4 = 0; c4 < 8; c4++) {
                ulonglong2 w = w2p[c4];
                o2a[2 * c4]     = fma2(hm2a, w.x, o2a[2 * c4]);
                o2a[2 * c4 + 1] = fma2(hm2a, w.y, o2a[2 * c4 + 1]);
                o2b[2 * c4]     = fma2(hm2b, w.x, o2b[2 * c4]);
                o2b[2 * c4 + 1] = fma2(hm2b, w.y, o2b[2 * c4 + 1]);
            }
        }
        #pragma unroll
        for (int c2 = 0; c2 < 16; c2++) {
            float lo, hi;
            unpack2(o2a[c2], lo, hi);
            s.s2[(2 * c2) * 513 + p0] = lo;
            s.s2[(2 * c2 + 1) * 513 + p0] = hi;
            unpack2(o2b[c2], lo, hi);
            s.s2[(2 * c2) * 513 + p1] = lo;
            s.s2[(2 * c2 + 1) * 513 + p1] = hi;
        }
    }
    __syncthreads();

    // ---- Phase 2: softmax per channel over P ----
    {
        const int warp = t >> 5, lane = t & 31;
        for (int c = warp * 4; c < warp * 4 + 4; c++) {
            float* row = s.s2 + c * 513;
            float m = -1e30f;
            for (int k = lane; k < PP; k += 32) m = fmaxf(m, row[k]);
            #pragma unroll
            for (int off = 16; off; off >>= 1)
                m = fmaxf(m, __shfl_xor_sync(0xffffffffu, m, off));
            float sum = 0.f;
            for (int k = lane; k < PP; k += 32) {
                float e = __expf(row[k] - m);
                row[k] = e;
                sum += e;
            }
            #pragma unroll
            for (int off = 16; off; off >>= 1)
                sum += __shfl_xor_sync(0xffffffffu, sum, off);
            float inv = 1.f / sum;
            for (int k = lane; k < PP; k += 32) row[k] *= inv;
        }
    }
    __syncthreads();

    // ---- Phase 3a: write attention heads 0..15 (vectorized STG.128) ----
    {
        float* attnbase = g_attn + scoreBase;
        // 16 heads x 512 p = 2048 float4 chunks; 8 per thread
        for (int i = t; i < HH * (PP / 4); i += 256) {
            int h = i >> 7;                 // 0..15
            int p4 = (i & 127) * 4;         // 0..508 step 4
            const float* row = s.s2 + h * 513 + p4;
            float4 v = make_float4(row[0], row[1], row[2], row[3]);
            *(float4*)(attnbase + (size_t)h * (LL * PP) + p4) = v;
        }
    }

    // ---- Phase 3b: displacement aggregation (heads 16..31) ----
    // 48 outputs x 4 lanes each (192 threads, 6 full warps); each lane sums a
    // 128-element quarter, then a lane-aligned shfl tree reduces the group.
    if (t < 192) {
        const int outIdx = t >> 2;          // 0..47
        const int sub = t & 3;              // quarter index
        const int d3 = outIdx / 16, h = outIdx % 16;
        const float xlv = (d3 == 0) ? xl0 : ((d3 == 1) ? xl1 : xl2);
        const float* arow = s.s2 + (16 + h) * 513;
        float acc = 0.f;
        const int pbeg = sub * 128;
        #pragma unroll 8
        for (int p = pbeg; p < pbeg + 128; p++)
            acc += arow[p] * (s.xp[p * 3 + d3] - xlv);
        acc += __shfl_xor_sync(0xffffffffu, acc, 1);
        acc += __shfl_xor_sync(0xffffffffu, acc, 2);
        if (sub == 0) s.odis[d3 * 16 + h] = acc;
    }
    __syncthreads();

    // ---- Phase 3c: displacement MLP 16 -> 32 (mish) -> 16 ----
    if (t < 48) {
        const int d3 = t / 16, ho = t % 16;
        float acc = s.bd2[ho];
        #pragma unroll 4
        for (int j = 0; j < 32; j++) {
            float tt = s.bd1[j];
            #pragma unroll
            for (int h = 0; h < 16; h++)
                tt += s.odis[d3 * 16 + h] * s.wd1[h * 32 + j];
            acc += mishf(tt) * s.wd2[j * 16 + ho];
        }
        out_dis[(size_t)blk * 48 + d3 * 16 + ho] = acc;
    }
}

// ---------------------------------------------------------------------------
// Launcher
// ---------------------------------------------------------------------------
extern "C" void kernel_launch(void* const* d_in, const int* in_sizes, int n_in,
                              void* d_out, int out_size)
{
    const float* h_ligand  = (const float*)d_in[0];
    const float* context   = (const float*)d_in[1];
    const float* x_protein = (const float*)d_in[2];
    const float* x_ligand  = (const float*)d_in[3];
    const float* w_qk      = (const float*)d_in[4];
    // d_in[5] = w_v (unused by reference)
    const float* w_cqk     = (const float*)d_in[6];
    const float* w_cv      = (const float*)d_in[7];
    const float* w_mlp1    = (const float*)d_in[8];
    const float* w_mlp2    = (const float*)d_in[9];
    const float* b_mlp2    = (const float*)d_in[10];
    const float* w_out     = (const float*)d_in[11];
    const float* b_out     = (const float*)d_in[12];
    const float* w_dis1    = (const float*)d_in[13];
    const float* b_dis1    = (const float*)d_in[14];
    const float* w_dis2    = (const float*)d_in[15];
    const float* b_dis2    = (const float*)d_in[16];
    const float* sigma     = (const float*)d_in[17];
    const float* w_pe1     = (const float*)d_in[18];
    const float* b_pe1     = (const float*)d_in[19];
    const float* w_pe2     = (const float*)d_in[20];
    const float* b_pe2     = (const float*)d_in[21];

    float* out = (float*)d_out;
    float* out_dis = out + BB * LL * DIMM;   // 131072 offset

    float *p_qk, *p_cqk, *p_cv, *p_sim, *p_attn, *p_outpre;
    cudaGetSymbolAddress((void**)&p_qk, g_qk);
    cudaGetSymbolAddress((void**)&p_cqk, g_cqk);
    cudaGetSymbolAddress((void**)&p_cv, g_cv);
    cudaGetSymbolAddress((void**)&p_sim, g_sim);
    cudaGetSymbolAddress((void**)&p_attn, g_attn);
    cudaGetSymbolAddress((void**)&p_outpre, g_outpre);

    static_assert(sizeof(SmemLayout) <= 110 * 1024, "smem overflow");
    cudaFuncSetAttribute(fused_attn_kernel,
                         cudaFuncAttributeMaxDynamicSharedMemorySize,
                         (int)sizeof(SmemLayout));

    // one-time weight transpose (overlaps with projections)
    prep_w1t<<<8, 256>>>(w_mlp1);

    // projections
    sgemm64<<<dim3(INNER / 64, (BB * LL) / 64), 256>>>(
        h_ligand, w_qk, p_qk, BB * LL, INNER, DIMM, nullptr);
    sgemm64<<<dim3(INNER / 64, (BB * PP) / 64), 256>>>(
        context, w_cqk, p_cqk, BB * PP, INNER, CDIMM, nullptr);
    sgemm64<<<dim3(INNER / 64, (BB * PP) / 64), 256>>>(
        context, w_cv, p_cv, BB * PP, INNER, CDIMM, nullptr);

    // scores: batched GEMM per (b,h)
    sim_kernel<<<BB * HH, 256>>>(p_qk, p_cqk, p_sim);

    // fused pointwise core + softmax + dis path
    fused_attn_kernel<<<BB * LL, 256, sizeof(SmemLayout)>>>(
        x_protein, x_ligand,
        w_mlp2, b_mlp2,
        w_dis1, b_dis1, w_dis2, b_dis2,
        sigma, w_pe1, b_pe1, w_pe2, b_pe2,
        out_dis);

    // attention-value aggregation: batched GEMM per (b,h)
    av_kernel<<<BB * HH, 128>>>(p_attn, p_cv, p_outpre);

    // output projection: [1024,512] @ [512,128] + bias
    sgemm64<<<dim3(DIMM / 64, (BB * LL) / 64), 256>>>(
        p_outpre, w_out, out, BB * LL, DIMM, INNER, b_out);
}

// round 15
// speedup vs baseline: 1.1524x; 1.1524x over previous
#include <cuda_runtime.h>
#include <cuda_bf16.h>
#include <cstdint>

// ---------------------------------------------------------------------------
// BottleneckModel decomposed implementation (fp32 + packed f32x2 FFMA)
// Shapes: B=16, L=64, P=512, H=16, DH=32, DIM=128, CDIM=256, inner=512, PEH=64
//
// R13/R14 change: sgemm128 (128x128x16 tile, 8x8 micro, NO A-duplication) for
// the three projections — the old sgemm64 was measured smem-bandwidth-bound
// (L1=88.6%, fma=32.4%). sgemm64 kept only for the small `out` GEMM.
//
// Canonical score layout: g_sim/g_attn element (b,h,l,p) at
//   ((b*16 + h)*64 + l)*512 + p
// ---------------------------------------------------------------------------

#define BB   16
#define LL   64
#define PP   512
#define HH   16
#define DHH  32
#define DIMM 128
#define CDIMM 256
#define INNER 512
#define PEH  64

typedef unsigned long long ull;

// Scratch (device globals; no allocation allowed)
__device__ float g_qk[BB * LL * INNER];          // [1024, 512]
__device__ float g_cqk[BB * PP * INNER];         // [8192, 512]
__device__ float g_cv[BB * PP * INNER];          // [8192, 512]
__device__ float g_sim[BB * HH * LL * PP];       // [b][h][l][p]
__device__ float g_attn[BB * HH * LL * PP];      // [b][h][l][p] (heads 0..15)
__device__ float g_outpre[BB * LL * INNER];      // [b*64+l][h*32+d]
__device__ float g_w1t[32 * 64];                 // transposed w_mlp1: [j][i]

// ---- packed fp32x2 helpers (Blackwell packed FFMA pipe) ----
__device__ __forceinline__ ull pack2(float lo, float hi) {
    ull r; asm("mov.b64 %0, {%1, %2};" : "=l"(r) : "f"(lo), "f"(hi)); return r;
}
__device__ __forceinline__ void unpack2(ull v, float& lo, float& hi) {
    asm("mov.b64 {%0, %1}, %2;" : "=f"(lo), "=f"(hi) : "l"(v));
}
__device__ __forceinline__ ull fma2(ull a, ull b, ull c) {
    ull d; asm("fma.rn.f32x2 %0, %1, %2, %3;" : "=l"(d) : "l"(a), "l"(b), "l"(c)); return d;
}

__device__ __forceinline__ float mishf(float x) {
    // mish(x) = x * tanh(softplus(x)) = x * (e^2 + 2e) / (e^2 + 2e + 2), e = exp(x)
    float e = __expf(fminf(x, 15.0f));
    float n = e * e + 2.0f * e;
    return x * __fdividef(n, n + 2.0f);
}

// ---------------------------------------------------------------------------
// prep kernel: w1t[j*32+i] = w_mlp1[i*64+j] (done once; blocks reload coalesced)
// ---------------------------------------------------------------------------
__global__ __launch_bounds__(256) void prep_w1t(const float* __restrict__ w_mlp1)
{
    int i = blockIdx.x * 256 + threadIdx.x;   // 2048 total
    if (i < 2048)
        g_w1t[i] = w_mlp1[((i & 31) << 6) + (i >> 5)];
}

// ---------------------------------------------------------------------------
// sgemm128: C[M,N] = A[M,K] @ B[K,N].  BM=BN=128, BK=16, 256 threads,
// 8x8 micro-tile, packed FFMA2, NO operand duplication in smem.
// Per kk: 4 LDS.128/thread (A half-warp-broadcast) vs 32 fma2 -> FMA-bound.
// Requires M%128==0, N%128==0, K%16==0.
// ---------------------------------------------------------------------------
__global__ __launch_bounds__(256) void sgemm128(
    const float* __restrict__ A, const float* __restrict__ Bm,
    float* __restrict__ C, int M, int N, int K)
{
    __shared__ float As[16][132];   // [kk][m], padded
    __shared__ float Bs[16][132];   // [kk][n], padded

    const int tid = threadIdx.x;
    const int row0 = blockIdx.y * 128, col0 = blockIdx.x * 128;
    const int mB = (tid >> 4) * 8;       // 0..120
    const int nB = (tid & 15) * 8;       // 0..120

    // global-load mapping (512 float4 per operand tile, 2 per thread)
    const int aRow0 = tid >> 2, aC4_0 = (tid & 3);
    const int aRow1 = (tid + 256) >> 2, aC4_1 = ((tid + 256) & 3);
    const int bRow0 = tid >> 5, bC4_0 = (tid & 31);
    const int bRow1 = (tid + 256) >> 5, bC4_1 = ((tid + 256) & 31);

    ull acc[8][4] = {};

    // prefetch tile 0
    float4 a0 = *(const float4*)(A + (size_t)(row0 + aRow0) * K + aC4_0 * 4);
    float4 a1 = *(const float4*)(A + (size_t)(row0 + aRow1) * K + aC4_1 * 4);
    float4 b0 = *(const float4*)(Bm + (size_t)bRow0 * N + col0 + bC4_0 * 4);
    float4 b1 = *(const float4*)(Bm + (size_t)bRow1 * N + col0 + bC4_1 * 4);

    for (int k0 = 0; k0 < K; k0 += 16) {
        // A stored transposed: As[k][m]
        As[aC4_0 * 4 + 0][aRow0] = a0.x;
        As[aC4_0 * 4 + 1][aRow0] = a0.y;
        As[aC4_0 * 4 + 2][aRow0] = a0.z;
        As[aC4_0 * 4 + 3][aRow0] = a0.w;
        As[aC4_1 * 4 + 0][aRow1] = a1.x;
        As[aC4_1 * 4 + 1][aRow1] = a1.y;
        As[aC4_1 * 4 + 2][aRow1] = a1.z;
        As[aC4_1 * 4 + 3][aRow1] = a1.w;
        *(float4*)(&Bs[bRow0][bC4_0 * 4]) = b0;
        *(float4*)(&Bs[bRow1][bC4_1 * 4]) = b1;
        __syncthreads();
        // prefetch next tile while computing this one
        if (k0 + 16 < K) {
            a0 = *(const float4*)(A + (size_t)(row0 + aRow0) * K + k0 + 16 + aC4_0 * 4);
            a1 = *(const float4*)(A + (size_t)(row0 + aRow1) * K + k0 + 16 + aC4_1 * 4);
            b0 = *(const float4*)(Bm + (size_t)(k0 + 16 + bRow0) * N + col0 + bC4_0 * 4);
            b1 = *(const float4*)(Bm + (size_t)(k0 + 16 + bRow1) * N + col0 + bC4_1 * 4);
        }
        #pragma unroll
        for (int kk = 0; kk < 16; kk++) {
            float4 af0 = *(const float4*)(&As[kk][mB]);
            float4 af1 = *(const float4*)(&As[kk][mB + 4]);
            ulonglong2 bf0 = *(const ulonglong2*)(&Bs[kk][nB]);
            ulonglong2 bf1 = *(const ulonglong2*)(&Bs[kk][nB + 4]);
            float am[8] = {af0.x, af0.y, af0.z, af0.w, af1.x, af1.y, af1.z, af1.w};
            #pragma unroll
            for (int m = 0; m < 8; m++) {
                ull amm = pack2(am[m], am[m]);
                acc[m][0] = fma2(amm, bf0.x, acc[m][0]);
                acc[m][1] = fma2(amm, bf0.y, acc[m][1]);
                acc[m][2] = fma2(amm, bf1.x, acc[m][2]);
                acc[m][3] = fma2(amm, bf1.y, acc[m][3]);
            }
        }
        __syncthreads();
    }

    #pragma unroll
    for (int m = 0; m < 8; m++) {
        float4 v0, v1;
        unpack2(acc[m][0], v0.x, v0.y);
        unpack2(acc[m][1], v0.z, v0.w);
        unpack2(acc[m][2], v1.x, v1.y);
        unpack2(acc[m][3], v1.z, v1.w);
        float* crow = C + (size_t)(row0 + mB + m) * N + col0 + nB;
        *(float4*)(crow)     = v0;
        *(float4*)(crow + 4) = v1;
    }
}

// ---------------------------------------------------------------------------
// Tiled SGEMM (64x64): kept for the small `out` projection (N=128).
// ---------------------------------------------------------------------------
__global__ __launch_bounds__(256) void sgemm64(
    const float* __restrict__ A, const float* __restrict__ Bm,
    float* __restrict__ C, int M, int N, int K, const float* __restrict__ bias)
{
    __shared__ ull  As2[16][64];   // A value duplicated into both halves
    __shared__ float Bs[16][64];

    const int tid = threadIdx.x;
    const int row0 = blockIdx.y * 64, col0 = blockIdx.x * 64;
    const int ty = tid / 16, tx = tid % 16;
    const int aRow = tid / 4, aCol = (tid % 4) * 4;
    const int bRow = tid / 16, bCol = (tid % 16) * 4;

    ull acc2[4][2] = {};

    float4 av = *(const float4*)(A + (size_t)(row0 + aRow) * K + aCol);
    float4 bvv = *(const float4*)(Bm + (size_t)bRow * N + col0 + bCol);

    for (int k0 = 0; k0 < K; k0 += 16) {
        As2[aCol + 0][aRow] = pack2(av.x, av.x);
        As2[aCol + 1][aRow] = pack2(av.y, av.y);
        As2[aCol + 2][aRow] = pack2(av.z, av.z);
        As2[aCol + 3][aRow] = pack2(av.w, av.w);
        *(float4*)(&Bs[bRow][bCol]) = bvv;
        __syncthreads();
        if (k0 + 16 < K) {
            av  = *(const float4*)(A + (size_t)(row0 + aRow) * K + k0 + 16 + aCol);
            bvv = *(const float4*)(Bm + (size_t)(k0 + 16 + bRow) * N + col0 + bCol);
        }
        #pragma unroll
        for (int kk = 0; kk < 16; kk++) {
            ulonglong2 bb = *(const ulonglong2*)(&Bs[kk][tx * 4]);
            const ulonglong2* arow = (const ulonglong2*)(&As2[kk][ty * 4]);
            ulonglong2 a01 = arow[0], a23 = arow[1];
            acc2[0][0] = fma2(a01.x, bb.x, acc2[0][0]);
            acc2[0][1] = fma2(a01.x, bb.y, acc2[0][1]);
            acc2[1][0] = fma2(a01.y, bb.x, acc2[1][0]);
            acc2[1][1] = fma2(a01.y, bb.y, acc2[1][1]);
            acc2[2][0] = fma2(a23.x, bb.x, acc2[2][0]);
            acc2[2][1] = fma2(a23.x, bb.y, acc2[2][1]);
            acc2[3][0] = fma2(a23.y, bb.x, acc2[3][0]);
            acc2[3][1] = fma2(a23.y, bb.y, acc2[3][1]);
        }
        __syncthreads();
    }

    float4 bv = make_float4(0.f, 0.f, 0.f, 0.f);
    if (bias) bv = *(const float4*)(bias + col0 + tx * 4);
    #pragma unroll
    for (int i = 0; i < 4; i++) {
        float4 v;
        unpack2(acc2[i][0], v.x, v.y);
        unpack2(acc2[i][1], v.z, v.w);
        v.x += bv.x; v.y += bv.y; v.z += bv.z; v.w += bv.w;
        *(float4*)(C + (size_t)(row0 + ty * 4 + i) * N + col0 + tx * 4) = v;
    }
}

// ---------------------------------------------------------------------------
// sim_kernel: per (b,h) block computes sim[b][h][l][p] = scale * qk . cqk
// ---------------------------------------------------------------------------
__global__ __launch_bounds__(256) void sim_kernel(
    const float* __restrict__ qk, const float* __restrict__ cqk,
    float* __restrict__ sim)
{
    const int blk = blockIdx.x, b = blk >> 4, h = blk & 15;
    __shared__ float aq[64][33];     // prescaled qk tile
    __shared__ float cq[128][33];
    const int t = threadIdx.x, ty = t >> 5, tx = t & 31;
    const float scale = 0.17677669529663687f;  // 32^-0.5

    for (int i = t; i < 2048; i += 256) {
        int l = i >> 5, d = i & 31;
        aq[l][d] = qk[((size_t)(b * 64 + l)) * INNER + h * 32 + d] * scale;
    }

    for (int p0 = 0; p0 < PP; p0 += 128) {
        __syncthreads();
        for (int i = t; i < 4096; i += 256) {
            int pp = i >> 5, d = i & 31;
            cq[pp][d] = cqk[((size_t)(b * PP + p0 + pp)) * INNER + h * 32 + d];
        }
        __syncthreads();
        ull acc2[8][2] = {};
        #pragma unroll 4
        for (int k = 0; k < 32; k++) {
            float c0 = cq[tx][k], c1 = cq[tx + 32][k];
            float c2 = cq[tx + 64][k], c3 = cq[tx + 96][k];
            ull cc0 = pack2(c0, c1), cc1 = pack2(c2, c3);
            #pragma unroll
            for (int i = 0; i < 8; i++) {
                float a = aq[ty * 8 + i][k];
                ull aa = pack2(a, a);
                acc2[i][0] = fma2(aa, cc0, acc2[i][0]);
                acc2[i][1] = fma2(aa, cc1, acc2[i][1]);
            }
        }
        #pragma unroll
        for (int i = 0; i < 8; i++) {
            float v0, v1, v2, v3;
            unpack2(acc2[i][0], v0, v1);
            unpack2(acc2[i][1], v2, v3);
            size_t base = ((size_t)(b * 16 + h) * 64 + ty * 8 + i) * PP + p0;
            sim[base + tx]      = v0;
            sim[base + tx + 32] = v1;
            sim[base + tx + 64] = v2;
            sim[base + tx + 96] = v3;
        }
    }
}

// ---------------------------------------------------------------------------
// av_kernel: per (b,h): outpre[l][d] = sum_p attn[b][h][l][p] * cv[b][p][h*32+d]
// ---------------------------------------------------------------------------
__global__ __launch_bounds__(128) void av_kernel(
    const float* __restrict__ attn, const float* __restrict__ cv,
    float* __restrict__ outpre)
{
    const int blk = blockIdx.x, b = blk >> 4, h = blk & 15;
    __shared__ float at[64][65];     // [l][k]
    __shared__ float cvs[64][36];    // [k][d]; stride 36 keeps dg*4 16B-aligned
    const int t = threadIdx.x;
    const int lg = t >> 3, dg = t & 7;

    ull acc2[4][2] = {};

    for (int k0 = 0; k0 < PP; k0 += 64) {
        __syncthreads();
        for (int i4 = t; i4 < 1024; i4 += 128) {
            int l = i4 >> 4, kk4 = (i4 & 15) * 4;
            float4 v = *(const float4*)(
                attn + ((size_t)(b * 16 + h) * 64 + l) * PP + k0 + kk4);
            at[l][kk4]     = v.x;
            at[l][kk4 + 1] = v.y;
            at[l][kk4 + 2] = v.z;
            at[l][kk4 + 3] = v.w;
        }
        for (int i = t; i < 2048; i += 128) {
            int kk = i >> 5, d = i & 31;
            cvs[kk][d] = cv[((size_t)(b * PP + k0 + kk)) * INNER + h * 32 + d];
        }
        __syncthreads();
        #pragma unroll 4
        for (int kk = 0; kk < 64; kk++) {
            ulonglong2 cc = *(const ulonglong2*)(&cvs[kk][dg * 4]);
            #pragma unroll
            for (int i = 0; i < 4; i++) {
                float a = at[lg * 4 + i][kk];
                ull aa = pack2(a, a);
                acc2[i][0] = fma2(aa, cc.x, acc2[i][0]);
                acc2[i][1] = fma2(aa, cc.y, acc2[i][1]);
            }
        }
    }

    #pragma unroll
    for (int i = 0; i < 4; i++) {
        float4 v;
        unpack2(acc2[i][0], v.x, v.y);
        unpack2(acc2[i][1], v.z, v.w);
        *(float4*)(outpre + ((size_t)(b * 64 + lg * 4 + i)) * INNER
                   + h * 32 + dg * 4) = v;
    }
}

// ---------------------------------------------------------------------------
// Fused core: one block per (b,l). 256 threads, 2-p joint MLP.
// ---------------------------------------------------------------------------
struct SmemLayout {
    float s2[32 * 513];
    float w1[32 * 64];       // TRANSPOSED: w1[j*32 + i] = w_mlp1[i*64 + j]
    float w2[64 * 32];
    float b2[32];
    float wp1[3 * 64];
    float bp1[64];
    float wp2[64 * 16];
    float bp2[16];
    float wd1[16 * 32];
    float bd1[32];
    float wd2[32 * 16];
    float bd2[16];
    float xp[PP * 3];
    float odis[48];
};

__global__ __launch_bounds__(256) void fused_attn_kernel(
    const float* __restrict__ x_protein,
    const float* __restrict__ x_ligand,
    const float* __restrict__ w_mlp2,
    const float* __restrict__ b_mlp2,
    const float* __restrict__ w_dis1, const float* __restrict__ b_dis1,
    const float* __restrict__ w_dis2, const float* __restrict__ b_dis2,
    const float* __restrict__ sigma,
    const float* __restrict__ w_pe1, const float* __restrict__ b_pe1,
    const float* __restrict__ w_pe2, const float* __restrict__ b_pe2,
    float* __restrict__ out_dis)
{
    extern __shared__ float smem_raw[];
    SmemLayout& s = *reinterpret_cast<SmemLayout*>(smem_raw);

    const int t = threadIdx.x;
    const int blk = blockIdx.x;          // b*L + l
    const int bb = blk / LL;
    const int ll = blk % LL;

    for (int i = t; i < 2048; i += 256) {
        s.w1[i] = g_w1t[i];
        s.w2[i] = w_mlp2[i];
    }
    for (int i = t; i < 1024; i += 256) s.wp2[i] = w_pe2[i];
    for (int i = t; i < 512; i += 256) { s.wd1[i] = w_dis1[i]; s.wd2[i] = w_dis2[i]; }
    if (t < 192) s.wp1[t] = w_pe1[t];
    if (t < 64)  s.bp1[t] = b_pe1[t];
    if (t < 32)  { s.b2[t] = b_mlp2[t]; s.bd1[t] = b_dis1[t]; }
    if (t < 16)  { s.bp2[t] = b_pe2[t]; s.bd2[t] = b_dis2[t]; }
    for (int i = t; i < PP * 3; i += 256)
        s.xp[i] = x_protein[(size_t)bb * PP * 3 + i];

    const float xl0 = x_ligand[blk * 3 + 0];
    const float xl1 = x_ligand[blk * 3 + 1];
    const float xl2 = x_ligand[blk * 3 + 2];
    const float sg = sigma[0];
    const float sfac = -0.5f / (sg * sg);
    __syncthreads();

    const size_t scoreBase = ((size_t)bb * (HH * LL) + ll) * PP;

    // ---- Phase 1: sim load + PE MLP + attn MLP for p0=t and p1=t+256 ----
    {
        const int p0 = t, p1 = t + 256;
        const float* simbase = g_sim + scoreBase;

        ull sc2a[16], sc2b[16];
        {
            float sha[16], shb[16];
            #pragma unroll
            for (int h = 0; h < HH; h++) {
                const float* r = simbase + (size_t)h * (LL * PP);
                sha[h] = r[p0];
                shb[h] = r[p1];
            }
            #pragma unroll
            for (int h2 = 0; h2 < 8; h2++) {
                sc2a[h2] = pack2(sha[2 * h2], sha[2 * h2 + 1]);
                sc2b[h2] = pack2(shb[2 * h2], shb[2 * h2 + 1]);
            }
        }

        float ea0 = __expf(sfac * (s.xp[p0 * 3 + 0] - xl0));
        float ea1 = __expf(sfac * (s.xp[p0 * 3 + 1] - xl1));
        float ea2 = __expf(sfac * (s.xp[p0 * 3 + 2] - xl2));
        float eb0 = __expf(sfac * (s.xp[p1 * 3 + 0] - xl0));
        float eb1 = __expf(sfac * (s.xp[p1 * 3 + 1] - xl1));
        float eb2 = __expf(sfac * (s.xp[p1 * 3 + 2] - xl2));

        #pragma unroll
        for (int h2 = 0; h2 < 8; h2++) {
            ull bv = pack2(s.bp2[2 * h2], s.bp2[2 * h2 + 1]);
            sc2a[8 + h2] = bv;
            sc2b[8 + h2] = bv;
        }

        #pragma unroll 1
        for (int j = 0; j < PEH; j++) {
            float w0 = s.wp1[j], w1v = s.wp1[64 + j], w2v = s.wp1[128 + j];
            float bj = s.bp1[j];
            float hma = mishf(bj + ea0 * w0 + ea1 * w1v + ea2 * w2v);
            float hmb = mishf(bj + eb0 * w0 + eb1 * w1v + eb2 * w2v);
            ull hm2a = pack2(hma, hma), hm2b = pack2(hmb, hmb);
            const ulonglong2* wp = (const ulonglong2*)(s.wp2 + j * 16);
            #pragma unroll
            for (int h4 = 0; h4 < 4; h4++) {
                ulonglong2 w = wp[h4];
                sc2a[8 + 2 * h4]     = fma2(hm2a, w.x, sc2a[8 + 2 * h4]);
                sc2a[8 + 2 * h4 + 1] = fma2(hm2a, w.y, sc2a[8 + 2 * h4 + 1]);
                sc2b[8 + 2 * h4]     = fma2(hm2b, w.x, sc2b[8 + 2 * h4]);
                sc2b[8 + 2 * h4 + 1] = fma2(hm2b, w.y, sc2b[8 + 2 * h4 + 1]);
            }
        }

        ull o2a[16], o2b[16];
        #pragma unroll
        for (int c2 = 0; c2 < 16; c2++) {
            ull bv = pack2(s.b2[2 * c2], s.b2[2 * c2 + 1]);
            o2a[c2] = bv;
            o2b[c2] = bv;
        }
        #pragma unroll 1
        for (int j = 0; j < 64; j++) {
            const ulonglong2* w1p = (const ulonglong2*)(s.w1 + j * 32);
            ull taa = 0ull, tab = 0ull, tba = 0ull, tbb = 0ull;
            #pragma unroll
            for (int i4 = 0; i4 < 8; i4++) {
                ulonglong2 w = w1p[i4];
                taa = fma2(sc2a[2 * i4],     w.x, taa);
                tab = fma2(sc2a[2 * i4 + 1], w.y, tab);
                tba = fma2(sc2b[2 * i4],     w.x, tba);
                tbb = fma2(sc2b[2 * i4 + 1], w.y, tbb);
            }
            float x0, x1, y0, y1;
            unpack2(taa, x0, x1); unpack2(tab, y0, y1);
            float hma = mishf((x0 + x1) + (y0 + y1));
            unpack2(tba, x0, x1); unpack2(tbb, y0, y1);
            float hmb = mishf((x0 + x1) + (y0 + y1));
            ull hm2a = pack2(hma, hma), hm2b = pack2(hmb, hmb);
            const ulonglong2* w2p = (const ulonglong2*)(s.w2 + j * 32);
            #pragma unroll
            for (int c4 = 0; c4 < 8; c4++) {
                ulonglong2 w = w2p[c4];
                o2a[2 * c4]     = fma2(hm2a, w.x, o2a[2 * c4]);
                o2a[2 * c4 + 1] = fma2(hm2a, w.y, o2a[2 * c4 + 1]);
                o2b[2 * c4]     = fma2(hm2b, w.x, o2b[2 * c4]);
                o2b[2 * c4 + 1] = fma2(hm2b, w.y, o2b[2 * c4 + 1]);
            }
        }
        #pragma unroll
        for (int c2 = 0; c2 < 16; c2++) {
            float lo, hi;
            unpack2(o2a[c2], lo, hi);
            s.s2[(2 * c2) * 513 + p0] = lo;
            s.s2[(2 * c2 + 1) * 513 + p0] = hi;
            unpack2(o2b[c2], lo, hi);
            s.s2[(2 * c2) * 513 + p1] = lo;
            s.s2[(2 * c2 + 1) * 513 + p1] = hi;
        }
    }
    __syncthreads();

    // ---- Phase 2: softmax per channel over P ----
    {
        const int warp = t >> 5, lane = t & 31;
        for (int c = warp * 4; c < warp * 4 + 4; c++) {
            float* row = s.s2 + c * 513;
            float m = -1e30f;
            for (int k = lane; k < PP; k += 32) m = fmaxf(m, row[k]);
            #pragma unroll
            for (int off = 16; off; off >>= 1)
                m = fmaxf(m, __shfl_xor_sync(0xffffffffu, m, off));
            float sum = 0.f;
            for (int k = lane; k < PP; k += 32) {
                float e = __expf(row[k] - m);
                row[k] = e;
                sum += e;
            }
            #pragma unroll
            for (int off = 16; off; off >>= 1)
                sum += __shfl_xor_sync(0xffffffffu, sum, off);
            float inv = 1.f / sum;
            for (int k = lane; k < PP; k += 32) row[k] *= inv;
        }
    }
    __syncthreads();

    // ---- Phase 3a: write attention heads 0..15 (vectorized STG.128) ----
    {
        float* attnbase = g_attn + scoreBase;
        for (int i = t; i < HH * (PP / 4); i += 256) {
            int h = i >> 7;
            int p4 = (i & 127) * 4;
            const float* row = s.s2 + h * 513 + p4;
            float4 v = make_float4(row[0], row[1], row[2], row[3]);
            *(float4*)(attnbase + (size_t)h * (LL * PP) + p4) = v;
        }
    }

    // ---- Phase 3b: displacement aggregation (heads 16..31) ----
    if (t < 192) {
        const int outIdx = t >> 2;
        const int sub = t & 3;
        const int d3 = outIdx / 16, h = outIdx % 16;
        const float xlv = (d3 == 0) ? xl0 : ((d3 == 1) ? xl1 : xl2);
        const float* arow = s.s2 + (16 + h) * 513;
        float acc = 0.f;
        const int pbeg = sub * 128;
        #pragma unroll 8
        for (int p = pbeg; p < pbeg + 128; p++)
            acc += arow[p] * (s.xp[p * 3 + d3] - xlv);
        acc += __shfl_xor_sync(0xffffffffu, acc, 1);
        acc += __shfl_xor_sync(0xffffffffu, acc, 2);
        if (sub == 0) s.odis[d3 * 16 + h] = acc;
    }
    __syncthreads();

    // ---- Phase 3c: displacement MLP 16 -> 32 (mish) -> 16 ----
    if (t < 48) {
        const int d3 = t / 16, ho = t % 16;
        float acc = s.bd2[ho];
        #pragma unroll 4
        for (int j = 0; j < 32; j++) {
            float tt = s.bd1[j];
            #pragma unroll
            for (int h = 0; h < 16; h++)
                tt += s.odis[d3 * 16 + h] * s.wd1[h * 32 + j];
            acc += mishf(tt) * s.wd2[j * 16 + ho];
        }
        out_dis[(size_t)blk * 48 + d3 * 16 + ho] = acc;
    }
}

// ---------------------------------------------------------------------------
// Launcher
// ---------------------------------------------------------------------------
extern "C" void kernel_launch(void* const* d_in, const int* in_sizes, int n_in,
                              void* d_out, int out_size)
{
    const float* h_ligand  = (const float*)d_in[0];
    const float* context   = (const float*)d_in[1];
    const float* x_protein = (const float*)d_in[2];
    const float* x_ligand  = (const float*)d_in[3];
    const float* w_qk      = (const float*)d_in[4];
    // d_in[5] = w_v (unused by reference)
    const float* w_cqk     = (const float*)d_in[6];
    const float* w_cv      = (const float*)d_in[7];
    const float* w_mlp1    = (const float*)d_in[8];
    const float* w_mlp2    = (const float*)d_in[9];
    const float* b_mlp2    = (const float*)d_in[10];
    const float* w_out     = (const float*)d_in[11];
    const float* b_out     = (const float*)d_in[12];
    const float* w_dis1    = (const float*)d_in[13];
    const float* b_dis1    = (const float*)d_in[14];
    const float* w_dis2    = (const float*)d_in[15];
    const float* b_dis2    = (const float*)d_in[16];
    const float* sigma     = (const float*)d_in[17];
    const float* w_pe1     = (const float*)d_in[18];
    const float* b_pe1     = (const float*)d_in[19];
    const float* w_pe2     = (const float*)d_in[20];
    const float* b_pe2     = (const float*)d_in[21];

    float* out = (float*)d_out;
    float* out_dis = out + BB * LL * DIMM;   // 131072 offset

    float *p_qk, *p_cqk, *p_cv, *p_sim, *p_attn, *p_outpre;
    cudaGetSymbolAddress((void**)&p_qk, g_qk);
    cudaGetSymbolAddress((void**)&p_cqk, g_cqk);
    cudaGetSymbolAddress((void**)&p_cv, g_cv);
    cudaGetSymbolAddress((void**)&p_sim, g_sim);
    cudaGetSymbolAddress((void**)&p_attn, g_attn);
    cudaGetSymbolAddress((void**)&p_outpre, g_outpre);

    static_assert(sizeof(SmemLayout) <= 110 * 1024, "smem overflow");
    cudaFuncSetAttribute(fused_attn_kernel,
                         cudaFuncAttributeMaxDynamicSharedMemorySize,
                         (int)sizeof(SmemLayout));

    // one-time weight transpose (overlaps with projections)
    prep_w1t<<<8, 256>>>(w_mlp1);

    // projections (128x128 tiles, FMA-bound)
    sgemm128<<<dim3(INNER / 128, (BB * LL) / 128), 256>>>(
        h_ligand, w_qk, p_qk, BB * LL, INNER, DIMM);
    sgemm128<<<dim3(INNER / 128, (BB * PP) / 128), 256>>>(
        context, w_cqk, p_cqk, BB * PP, INNER, CDIMM);
    sgemm128<<<dim3(INNER / 128, (BB * PP) / 128), 256>>>(
        context, w_cv, p_cv, BB * PP, INNER, CDIMM);

    // scores: batched GEMM per (b,h)
    sim_kernel<<<BB * HH, 256>>>(p_qk, p_cqk, p_sim);

    // fused pointwise core + softmax + dis path
    fused_attn_kernel<<<BB * LL, 256, sizeof(SmemLayout)>>>(
        x_protein, x_ligand,
        w_mlp2, b_mlp2,
        w_dis1, b_dis1, w_dis2, b_dis2,
        sigma, w_pe1, b_pe1, w_pe2, b_pe2,
        out_dis);

    // attention-value aggregation: batched GEMM per (b,h)
    av_kernel<<<BB * HH, 128>>>(p_attn, p_cv, p_outpre);

    // output projection: [1024,512] @ [512,128] + bias
    sgemm64<<<dim3(DIMM / 64, (BB * LL) / 64), 256>>>(
        p_outpre, w_out, out, BB * LL, DIMM, INNER, b_out);
}